// round 4
// baseline (speedup 1.0000x reference)
#include <cuda_runtime.h>

// LightGCN propagation: 2 layers, push-SpMM with vector atomics.
//
// Inputs (metadata order):
//   0: user_emb0  float32 [100000*64]
//   1: item_emb0  float32 [50000*64]
//   2: a_ui_vals  float32 [E]
//   3: a_iu_vals  float32 [E]
//   4: edge_u     int32   [E]
//   5: edge_i     int32   [E]
// Output float32, laid out as:
//   user stack [3,100000,64] followed by item stack [3,50000,64]

#define N_USERS 100000
#define N_ITEMS 50000
#define DIM     64
#define N_EDGES 3200000
#define ALPHA   0.1f

// -------------------------------------------------------------------------
// Init: copy layer0 and seed layers 1,2 with ALPHA*emb0 (float4 granularity).
// -------------------------------------------------------------------------
__global__ void init_stack(const float4* __restrict__ emb0,
                           float4* __restrict__ out, int n4) {
    int idx = blockIdx.x * blockDim.x + threadIdx.x;
    if (idx >= n4) return;
    float4 v = emb0[idx];
    out[idx] = v;
    float4 s = make_float4(ALPHA * v.x, ALPHA * v.y, ALPHA * v.z, ALPHA * v.w);
    out[idx + n4]     = s;
    out[idx + 2 * n4] = s;
}

// -------------------------------------------------------------------------
// Push SpMM: dst[dst_idx[e]] += vals[e] * src[src_idx[e]]
// 16 threads per edge, one float4 lane each. Scatter via red.global.add.v4.f32
// (REDG.128, no return) so the LTS atomic path runs at 16B per op.
// -------------------------------------------------------------------------
__global__ void __launch_bounds__(256)
spmm_push(const float* __restrict__ vals,
          const int*   __restrict__ dst_idx,
          const int*   __restrict__ src_idx,
          const float4* __restrict__ src,
          float4* __restrict__ dst) {
    int t = blockIdx.x * blockDim.x + threadIdx.x;          // E*16 = 51.2M < 2^31
    if (t >= N_EDGES * 16) return;
    int e = t >> 4;
    int c = t & 15;

    float v = __ldg(&vals[e]);
    int   s = __ldg(&src_idx[e]);
    int   d = __ldg(&dst_idx[e]);

    float4 x = __ldg(&src[s * 16 + c]);
    float4 y = make_float4(v * x.x, v * x.y, v * x.z, v * x.w);

    const float4* p = &dst[d * 16 + c];
    asm volatile("red.global.add.v4.f32 [%0], {%1, %2, %3, %4};"
                 :: "l"(p), "f"(y.x), "f"(y.y), "f"(y.z), "f"(y.w)
                 : "memory");
}

extern "C" void kernel_launch(void* const* d_in, const int* in_sizes, int n_in,
                              void* d_out, int out_size) {
    const float* user_emb0 = (const float*)d_in[0];
    const float* item_emb0 = (const float*)d_in[1];
    const float* a_ui_vals = (const float*)d_in[2];
    const float* a_iu_vals = (const float*)d_in[3];
    const int*   edge_u    = (const int*)d_in[4];
    const int*   edge_i    = (const int*)d_in[5];

    float* out = (float*)d_out;

    const long long USZ = (long long)N_USERS * DIM;   // one user layer
    const long long ISZ = (long long)N_ITEMS * DIM;   // one item layer
    float* u_stack = out;                 // [3, N_USERS, D]
    float* i_stack = out + 3 * USZ;       // [3, N_ITEMS, D]

    float* u1 = u_stack + USZ;
    float* u2 = u_stack + 2 * USZ;
    float* i1 = i_stack + ISZ;
    float* i2 = i_stack + 2 * ISZ;

    // --- init layer stacks -------------------------------------------------
    {
        int n4u = N_USERS * DIM / 4;
        int n4i = N_ITEMS * DIM / 4;
        init_stack<<<(n4u + 255) / 256, 256>>>((const float4*)user_emb0,
                                               (float4*)u_stack, n4u);
        init_stack<<<(n4i + 255) / 256, 256>>>((const float4*)item_emb0,
                                               (float4*)i_stack, n4i);
    }

    const int spmm_threads = 256;
    const int spmm_blocks  = (N_EDGES * 16 + spmm_threads - 1) / spmm_threads;

    // --- layer 1 (reads layer-0 = original embeddings) ----------------------
    spmm_push<<<spmm_blocks, spmm_threads>>>(a_ui_vals, edge_u, edge_i,
                                             (const float4*)item_emb0,
                                             (float4*)u1);
    spmm_push<<<spmm_blocks, spmm_threads>>>(a_iu_vals, edge_i, edge_u,
                                             (const float4*)user_emb0,
                                             (float4*)i1);

    // --- layer 2 (reads layer-1 results) ------------------------------------
    spmm_push<<<spmm_blocks, spmm_threads>>>(a_ui_vals, edge_u, edge_i,
                                             (const float4*)i1,
                                             (float4*)u2);
    spmm_push<<<spmm_blocks, spmm_threads>>>(a_iu_vals, edge_i, edge_u,
                                             (const float4*)u1,
                                             (float4*)i2);
}

// round 7
// speedup vs baseline: 1.2893x; 1.2893x over previous
#include <cuda_runtime.h>

// LightGCN propagation, round 7 (resubmit — broker never ran rounds 5/6):
// fused per-layer SpMM pair + 2-edge ILP batching.
//
// Inputs (metadata order):
//   0: user_emb0  float32 [100000*64]
//   1: item_emb0  float32 [50000*64]
//   2: a_ui_vals  float32 [E]
//   3: a_iu_vals  float32 [E]
//   4: edge_u     int32   [E]
//   5: edge_i     int32   [E]
// Output float32: user stack [3,100000,64] then item stack [3,50000,64]

#define N_USERS 100000
#define N_ITEMS 50000
#define DIM     64
#define N_EDGES 3200000
#define ALPHA   0.1f

// 16 threads per edge (one float4 chunk each), 2 edges per thread.
// Block = 256 threads -> 16 edge slots -> 32 edges/block -> E/32 = 100000 blocks.
#define SLOTS            16
#define EDGES_PER_THREAD 2
#define EDGES_PER_BLOCK  (SLOTS * EDGES_PER_THREAD)   // 32

__device__ __forceinline__ void red_add_v4(float4* p, float4 y) {
    asm volatile("red.global.add.v4.f32 [%0], {%1, %2, %3, %4};"
                 :: "l"(p), "f"(y.x), "f"(y.y), "f"(y.z), "f"(y.w)
                 : "memory");
}

// -------------------------------------------------------------------------
// Init: copy layer0 and seed layers 1,2 with ALPHA*emb0.
// -------------------------------------------------------------------------
__global__ void init_stack(const float4* __restrict__ emb0,
                           float4* __restrict__ out, int n4) {
    int idx = blockIdx.x * blockDim.x + threadIdx.x;
    if (idx >= n4) return;
    float4 v = emb0[idx];
    out[idx] = v;
    float4 s = make_float4(ALPHA * v.x, ALPHA * v.y, ALPHA * v.z, ALPHA * v.w);
    out[idx + n4]     = s;
    out[idx + 2 * n4] = s;
}

// -------------------------------------------------------------------------
// One propagation layer, both directions fused:
//   udst[u] += a_ui[e] * isrc[i]      (u = edge_u[e], i = edge_i[e])
//   idst[i] += a_iu[e] * usrc[u]
// Front-batched index loads, then 4 independent gathers, then 4 REDG.v4.
// -------------------------------------------------------------------------
__global__ void __launch_bounds__(256)
layer_fused(const float* __restrict__ a_ui,
            const float* __restrict__ a_iu,
            const int*   __restrict__ edge_u,
            const int*   __restrict__ edge_i,
            const float4* __restrict__ usrc,   // user-side rows (indexed by u)
            const float4* __restrict__ isrc,   // item-side rows (indexed by i)
            float4* __restrict__ udst,
            float4* __restrict__ idst) {
    const int c = threadIdx.x & (SLOTS - 1);          // float4 chunk within row
    const int g = threadIdx.x >> 4;                   // edge slot 0..15
    const int ebase = blockIdx.x * EDGES_PER_BLOCK + g;

    const int e0 = ebase;
    const int e1 = ebase + SLOTS;

    // --- phase 1: edge metadata (all independent) ---------------------------
    int   u0  = __ldg(&edge_u[e0]);
    int   u1  = __ldg(&edge_u[e1]);
    int   i0  = __ldg(&edge_i[e0]);
    int   i1  = __ldg(&edge_i[e1]);
    float vu0 = __ldg(&a_ui[e0]);
    float vu1 = __ldg(&a_ui[e1]);
    float vi0 = __ldg(&a_iu[e0]);
    float vi1 = __ldg(&a_iu[e1]);

    // --- phase 2: 4 independent row gathers --------------------------------
    float4 xi0 = __ldg(&isrc[i0 * SLOTS + c]);   // feeds u-update, edge 0
    float4 xi1 = __ldg(&isrc[i1 * SLOTS + c]);   // feeds u-update, edge 1
    float4 xu0 = __ldg(&usrc[u0 * SLOTS + c]);   // feeds i-update, edge 0
    float4 xu1 = __ldg(&usrc[u1 * SLOTS + c]);   // feeds i-update, edge 1

    // --- phase 3: scale + scatter (REDG.128, no return) ---------------------
    float4 y;
    y = make_float4(vu0 * xi0.x, vu0 * xi0.y, vu0 * xi0.z, vu0 * xi0.w);
    red_add_v4(&udst[u0 * SLOTS + c], y);
    y = make_float4(vu1 * xi1.x, vu1 * xi1.y, vu1 * xi1.z, vu1 * xi1.w);
    red_add_v4(&udst[u1 * SLOTS + c], y);
    y = make_float4(vi0 * xu0.x, vi0 * xu0.y, vi0 * xu0.z, vi0 * xu0.w);
    red_add_v4(&idst[i0 * SLOTS + c], y);
    y = make_float4(vi1 * xu1.x, vi1 * xu1.y, vi1 * xu1.z, vi1 * xu1.w);
    red_add_v4(&idst[i1 * SLOTS + c], y);
}

extern "C" void kernel_launch(void* const* d_in, const int* in_sizes, int n_in,
                              void* d_out, int out_size) {
    const float* user_emb0 = (const float*)d_in[0];
    const float* item_emb0 = (const float*)d_in[1];
    const float* a_ui_vals = (const float*)d_in[2];
    const float* a_iu_vals = (const float*)d_in[3];
    const int*   edge_u    = (const int*)d_in[4];
    const int*   edge_i    = (const int*)d_in[5];

    float* out = (float*)d_out;

    const long long USZ = (long long)N_USERS * DIM;
    const long long ISZ = (long long)N_ITEMS * DIM;
    float* u_stack = out;                 // [3, N_USERS, D]
    float* i_stack = out + 3 * USZ;       // [3, N_ITEMS, D]

    float* u1 = u_stack + USZ;
    float* u2 = u_stack + 2 * USZ;
    float* i1 = i_stack + ISZ;
    float* i2 = i_stack + 2 * ISZ;

    // --- init layer stacks (copy layer0, seed layers 1,2 with ALPHA*emb0) ---
    {
        int n4u = N_USERS * DIM / 4;
        int n4i = N_ITEMS * DIM / 4;
        init_stack<<<(n4u + 255) / 256, 256>>>((const float4*)user_emb0,
                                               (float4*)u_stack, n4u);
        init_stack<<<(n4i + 255) / 256, 256>>>((const float4*)item_emb0,
                                               (float4*)i_stack, n4i);
    }

    // N_EDGES = 3,200,000 = 100,000 * EDGES_PER_BLOCK exactly -> no tail.
    const int blocks = N_EDGES / EDGES_PER_BLOCK;

    // --- layer 1: reads layer-0 embeddings, accumulates into u1/i1 ----------
    layer_fused<<<blocks, 256>>>(a_ui_vals, a_iu_vals, edge_u, edge_i,
                                 (const float4*)user_emb0,
                                 (const float4*)item_emb0,
                                 (float4*)u1, (float4*)i1);

    // --- layer 2: reads u1/i1, accumulates into u2/i2 ------------------------
    layer_fused<<<blocks, 256>>>(a_ui_vals, a_iu_vals, edge_u, edge_i,
                                 (const float4*)u1,
                                 (const float4*)i1,
                                 (float4*)u2, (float4*)i2);
}

// round 9
// speedup vs baseline: 2.0746x; 1.6090x over previous
#include <cuda_runtime.h>

// LightGCN, round 9 (resubmit of round-8 pull design; broker never ran it).
// Pull-based SpMM via per-launch bucketed adjacency.
//
// Inputs: 0 user_emb0 [100000*64], 1 item_emb0 [50000*64], 2 a_ui_vals [E],
//         3 a_iu_vals [E], 4 edge_u [E], 5 edge_i [E]
// Output float32: user stack [3,100000,64] then item stack [3,50000,64]

#define N_USERS 100000
#define N_ITEMS 50000
#define DIM     64
#define N_EDGES 3200000
#define ALPHA   0.1f

// Fixed-capacity adjacency buckets. Degrees ~ Poisson(32) users / Poisson(64)
// items; P(deg > cap) < 1e-40 — guarded anyway.
#define UCAP 160
#define ICAP 256

// Scratch (device globals — no allocation allowed). 16B-aligned: the pull
// loop reads records with LDG.128 (int4).
__device__ int  g_ucnt[N_USERS];
__device__ int  g_icnt[N_ITEMS];
__device__ __align__(16) int2 g_uslots[(size_t)N_USERS * UCAP];  // (item, a_ui)
__device__ __align__(16) int2 g_islots[(size_t)N_ITEMS * ICAP];  // (user, a_iu)

// -------------------------------------------------------------------------
__global__ void zero_cnts() {
    int idx = blockIdx.x * blockDim.x + threadIdx.x;
    if (idx < N_USERS) g_ucnt[idx] = 0;
    if (idx < N_ITEMS) g_icnt[idx] = 0;
}

// -------------------------------------------------------------------------
// Bucket every edge into both adjacency lists.
// -------------------------------------------------------------------------
__global__ void __launch_bounds__(256)
fill_slots(const float* __restrict__ a_ui, const float* __restrict__ a_iu,
           const int* __restrict__ edge_u, const int* __restrict__ edge_i) {
    int e = blockIdx.x * blockDim.x + threadIdx.x;
    if (e >= N_EDGES) return;
    int   u  = __ldg(&edge_u[e]);
    int   i  = __ldg(&edge_i[e]);
    float vu = __ldg(&a_ui[e]);
    float vi = __ldg(&a_iu[e]);
    int pu = atomicAdd(&g_ucnt[u], 1);
    if (pu < UCAP) g_uslots[(size_t)u * UCAP + pu] = make_int2(i, __float_as_int(vu));
    int pi = atomicAdd(&g_icnt[i], 1);
    if (pi < ICAP) g_islots[(size_t)i * ICAP + pi] = make_int2(u, __float_as_int(vi));
}

// -------------------------------------------------------------------------
// One propagation layer, pull mode. 16 lanes per destination row (one float4
// chunk each), 16 rows per 256-thread block. Rows [0,N_USERS) are users,
// [N_USERS, N_USERS+N_ITEMS) are items. acc starts at ALPHA*emb0 (seed fused).
// -------------------------------------------------------------------------
__global__ void __launch_bounds__(256, 6)
pull_layer(const float4* __restrict__ usrc, const float4* __restrict__ isrc,
           const float4* __restrict__ uemb0, const float4* __restrict__ iemb0,
           float4* __restrict__ udst, float4* __restrict__ idst) {
    const int gidx = blockIdx.x * 16 + (threadIdx.x >> 4);  // global row id
    const int c    = threadIdx.x & 15;                      // float4 chunk

    const bool isu = gidx < N_USERS;
    const int  row = isu ? gidx : gidx - N_USERS;

    const int2*   slots;
    const float4* src;
    const float4* e0;
    float4*       dst;
    int           cnt;
    if (isu) {
        slots = g_uslots + (size_t)row * UCAP;
        cnt   = g_ucnt[row];
        src   = isrc;  e0 = uemb0;  dst = udst;   // users gather item rows
    } else {
        slots = g_islots + (size_t)row * ICAP;
        cnt   = g_icnt[row];
        src   = usrc;  e0 = iemb0;  dst = idst;   // items gather user rows
    }

    float4 b = __ldg(&e0[row * 16 + c]);
    float4 acc0 = make_float4(ALPHA * b.x, ALPHA * b.y, ALPHA * b.z, ALPHA * b.w);
    float4 acc1 = make_float4(0.f, 0.f, 0.f, 0.f);

    // Unroll 4: two int4 record loads (2 records each, broadcast across the
    // 16-lane group) feed 4 independent row gathers; 2 accumulator chains.
    const int4* s4 = (const int4*)slots;   // 16B-aligned (see declarations)
    int j = 0;
    for (; j + 4 <= cnt; j += 4) {
        int4 r01 = __ldg(&s4[(j >> 1) + 0]);   // records j, j+1
        int4 r23 = __ldg(&s4[(j >> 1) + 1]);   // records j+2, j+3
        float4 x0 = __ldg(&src[(size_t)r01.x * 16 + c]);
        float4 x1 = __ldg(&src[(size_t)r01.z * 16 + c]);
        float4 x2 = __ldg(&src[(size_t)r23.x * 16 + c]);
        float4 x3 = __ldg(&src[(size_t)r23.z * 16 + c]);
        float v0 = __int_as_float(r01.y), v1 = __int_as_float(r01.w);
        float v2 = __int_as_float(r23.y), v3 = __int_as_float(r23.w);
        acc0.x += v0 * x0.x; acc0.y += v0 * x0.y; acc0.z += v0 * x0.z; acc0.w += v0 * x0.w;
        acc1.x += v1 * x1.x; acc1.y += v1 * x1.y; acc1.z += v1 * x1.z; acc1.w += v1 * x1.w;
        acc0.x += v2 * x2.x; acc0.y += v2 * x2.y; acc0.z += v2 * x2.z; acc0.w += v2 * x2.w;
        acc1.x += v3 * x3.x; acc1.y += v3 * x3.y; acc1.z += v3 * x3.z; acc1.w += v3 * x3.w;
    }
    for (; j < cnt; j++) {
        int2 r = __ldg(&slots[j]);
        float4 x = __ldg(&src[(size_t)r.x * 16 + c]);
        float v = __int_as_float(r.y);
        acc0.x += v * x.x; acc0.y += v * x.y; acc0.z += v * x.z; acc0.w += v * x.w;
    }

    float4 acc = make_float4(acc0.x + acc1.x, acc0.y + acc1.y,
                             acc0.z + acc1.z, acc0.w + acc1.w);
    dst[row * 16 + c] = acc;
}

extern "C" void kernel_launch(void* const* d_in, const int* in_sizes, int n_in,
                              void* d_out, int out_size) {
    const float* user_emb0 = (const float*)d_in[0];
    const float* item_emb0 = (const float*)d_in[1];
    const float* a_ui_vals = (const float*)d_in[2];
    const float* a_iu_vals = (const float*)d_in[3];
    const int*   edge_u    = (const int*)d_in[4];
    const int*   edge_i    = (const int*)d_in[5];

    float* out = (float*)d_out;
    const long long USZ = (long long)N_USERS * DIM;
    const long long ISZ = (long long)N_ITEMS * DIM;
    float* u_stack = out;                 // [3, N_USERS, D]
    float* i_stack = out + 3 * USZ;       // [3, N_ITEMS, D]

    float* u0 = u_stack;          float* i0 = i_stack;
    float* u1 = u_stack + USZ;    float* i1 = i_stack + ISZ;
    float* u2 = u_stack + 2*USZ;  float* i2 = i_stack + 2*ISZ;

    // --- build adjacency (every launch; stateless) --------------------------
    zero_cnts<<<(N_USERS + 255) / 256, 256>>>();
    fill_slots<<<(N_EDGES + 255) / 256, 256>>>(a_ui_vals, a_iu_vals,
                                               edge_u, edge_i);

    // --- layer 0 copies -----------------------------------------------------
    cudaMemcpyAsync(u0, user_emb0, USZ * sizeof(float), cudaMemcpyDeviceToDevice);
    cudaMemcpyAsync(i0, item_emb0, ISZ * sizeof(float), cudaMemcpyDeviceToDevice);

    // --- propagation: (N_USERS + N_ITEMS) rows, 16 rows per block -----------
    const int blocks = (N_USERS + N_ITEMS) / 16;   // 150000/16 = 9375 exactly

    pull_layer<<<blocks, 256>>>((const float4*)user_emb0, (const float4*)item_emb0,
                                (const float4*)user_emb0, (const float4*)item_emb0,
                                (float4*)u1, (float4*)i1);

    pull_layer<<<blocks, 256>>>((const float4*)u1, (const float4*)i1,
                                (const float4*)user_emb0, (const float4*)item_emb0,
                                (float4*)u2, (float4*)i2);
}